// round 2
// baseline (speedup 1.0000x reference)
#include <cuda_runtime.h>
#include <math.h>

// ---------------------------------------------------------------------------
// QuantumAttention: B=2, L=2048, D=512, H=8, Dh=64
// out = (out_real[B,L,D], out_imag[B,L,D], attention[B,H,L,L]) concatenated
// ---------------------------------------------------------------------------

namespace {
constexpr int QB = 2, QL = 2048, QD = 512, QH = 8, QDh = 64;
constexpr int QBH = QB * QH;                       // 16
constexpr size_t RIOFF = (size_t)QB * QH * QL * QDh;   // 2,097,152 (real/imag plane)
constexpr size_t QSZ   = 2 * RIOFF;                    // 4,194,304
constexpr size_t SSZ   = (size_t)QBH * QL * QL;        // 67,108,864
}

// Scratch (device globals: no runtime allocation allowed)
__device__ float g_Q[QSZ];
__device__ float g_K[QSZ];
__device__ float g_V[QSZ];
__device__ float g_Sr[SSZ];
__device__ float g_Si[SSZ];
__device__ float g_m[QBH * QL];
__device__ float g_il[QBH * QL];
__device__ float g_Or[(size_t)QB * QL * QD];
__device__ float g_Oi[(size_t)QB * QL * QD];

// ---------------------------------------------------------------------------
// GEMM: C[r,c] = sum_k X[r,k] * W[c,k] + bias[c], K = N = 512.
// MODE 0: X rows 0..4095 from X0 (wave_real), 4096..8191 from X1 (wave_imag);
//         output scattered to g_Q/g_K/g_V (sel) in [ri][b][h][l][dh] layout.
// MODE 1: X = g_Or (sel=0) / g_Oi (sel=1); output row-major to Yext.
// Block tile 128x128, K-tile 8, 256 threads, 8x8 per-thread micro-tile.
// ---------------------------------------------------------------------------
template <int MODE>
__global__ __launch_bounds__(256) void gemm128(
    const float* __restrict__ X0, const float* __restrict__ X1,
    const float* __restrict__ Wt, const float* __restrict__ bias,
    float* __restrict__ Yext, int sel)
{
    __shared__ float As[8][128];
    __shared__ float Bs[8][128];

    const int tid = threadIdx.x;
    const int r0 = blockIdx.y * 128;
    const int c0 = blockIdx.x * 128;

    const float* X;
    int rbase = r0;
    if (MODE == 0) {
        if (r0 >= 4096) { X = X1; rbase = r0 - 4096; }
        else            { X = X0; }
    } else {
        X = sel ? g_Oi : g_Or;
    }

    const int lr = tid >> 1;          // 0..127
    const int lc = (tid & 1) << 2;    // 0 or 4
    const int ty = tid >> 4;          // 0..15
    const int tx = tid & 15;          // 0..15

    float acc[8][8];
    #pragma unroll
    for (int i = 0; i < 8; i++)
        #pragma unroll
        for (int j = 0; j < 8; j++) acc[i][j] = 0.f;

    const float* Arow = X  + (size_t)(rbase + lr) * 512 + lc;
    const float* Brow = Wt + (size_t)(c0 + lr) * 512 + lc;

    for (int k0 = 0; k0 < 512; k0 += 8) {
        float4 a = *(const float4*)(Arow + k0);
        float4 b = *(const float4*)(Brow + k0);
        As[lc + 0][lr] = a.x; As[lc + 1][lr] = a.y;
        As[lc + 2][lr] = a.z; As[lc + 3][lr] = a.w;
        Bs[lc + 0][lr] = b.x; Bs[lc + 1][lr] = b.y;
        Bs[lc + 2][lr] = b.z; Bs[lc + 3][lr] = b.w;
        __syncthreads();
        #pragma unroll
        for (int k = 0; k < 8; k++) {
            float av[8], bv[8];
            *(float4*)&av[0] = *(const float4*)&As[k][ty * 8];
            *(float4*)&av[4] = *(const float4*)&As[k][ty * 8 + 4];
            *(float4*)&bv[0] = *(const float4*)&Bs[k][tx * 8];
            *(float4*)&bv[4] = *(const float4*)&Bs[k][tx * 8 + 4];
            #pragma unroll
            for (int i = 0; i < 8; i++)
                #pragma unroll
                for (int j = 0; j < 8; j++)
                    acc[i][j] = fmaf(av[i], bv[j], acc[i][j]);
        }
        __syncthreads();
    }

    #pragma unroll
    for (int i = 0; i < 8; i++) {
        const int r = r0 + ty * 8 + i;
        #pragma unroll
        for (int j = 0; j < 8; j++) {
            const int c = c0 + tx * 8 + j;
            float v = acc[i][j] + bias[c];
            if (MODE == 0) {
                const int ri = r >> 12;
                const int bl = r & 4095;
                const int bb = bl >> 11;
                const int l  = bl & 2047;
                const int h  = c >> 6;
                const int dh = c & 63;
                size_t idx = ((((size_t)ri * QB + bb) * QH + h) * QL + l) * QDh + dh;
                float* dst = (sel == 0) ? g_Q : (sel == 1) ? g_K : g_V;
                dst[idx] = v;
            } else {
                Yext[(size_t)r * 512 + c] = v;
            }
        }
    }
}

// ---------------------------------------------------------------------------
// QK: Sr = Qr Kr^T + Qi Ki^T ; Si = Qr Ki^T - Qi Kr^T, per (b,h).
// Block: 64 q-rows x 64 k-cols, full Dh=64 in 4 chunks of 16.
// ---------------------------------------------------------------------------
__global__ __launch_bounds__(256) void qk_kernel()
{
    __shared__ float Qrs[16][68], Qis[16][68], Krs[16][68], Kis[16][68];

    const int bh = blockIdx.z;
    const int q0 = blockIdx.y * 64;
    const int k0 = blockIdx.x * 64;
    const size_t hb = (size_t)bh * QL * QDh;
    const float* Qr = g_Q + hb;
    const float* Qi = g_Q + hb + RIOFF;
    const float* Kr = g_K + hb;
    const float* Ki = g_K + hb + RIOFF;

    const int tid = threadIdx.x;
    const int lr = tid >> 2;          // 0..63
    const int lc = (tid & 3) << 2;    // 0,4,8,12
    const int ty = tid >> 4;          // 0..15
    const int tx = tid & 15;          // 0..15

    float sr[4][4], si[4][4];
    #pragma unroll
    for (int i = 0; i < 4; i++)
        #pragma unroll
        for (int j = 0; j < 4; j++) { sr[i][j] = 0.f; si[i][j] = 0.f; }

    for (int d0 = 0; d0 < 64; d0 += 16) {
        float4 aqr = *(const float4*)(Qr + (size_t)(q0 + lr) * QDh + d0 + lc);
        float4 aqi = *(const float4*)(Qi + (size_t)(q0 + lr) * QDh + d0 + lc);
        float4 akr = *(const float4*)(Kr + (size_t)(k0 + lr) * QDh + d0 + lc);
        float4 aki = *(const float4*)(Ki + (size_t)(k0 + lr) * QDh + d0 + lc);
        Qrs[lc + 0][lr] = aqr.x; Qrs[lc + 1][lr] = aqr.y;
        Qrs[lc + 2][lr] = aqr.z; Qrs[lc + 3][lr] = aqr.w;
        Qis[lc + 0][lr] = aqi.x; Qis[lc + 1][lr] = aqi.y;
        Qis[lc + 2][lr] = aqi.z; Qis[lc + 3][lr] = aqi.w;
        Krs[lc + 0][lr] = akr.x; Krs[lc + 1][lr] = akr.y;
        Krs[lc + 2][lr] = akr.z; Krs[lc + 3][lr] = akr.w;
        Kis[lc + 0][lr] = aki.x; Kis[lc + 1][lr] = aki.y;
        Kis[lc + 2][lr] = aki.z; Kis[lc + 3][lr] = aki.w;
        __syncthreads();
        #pragma unroll
        for (int kk = 0; kk < 16; kk++) {
            float qr[4], qi[4], kr[4], ki[4];
            *(float4*)qr = *(const float4*)&Qrs[kk][ty * 4];
            *(float4*)qi = *(const float4*)&Qis[kk][ty * 4];
            *(float4*)kr = *(const float4*)&Krs[kk][tx * 4];
            *(float4*)ki = *(const float4*)&Kis[kk][tx * 4];
            #pragma unroll
            for (int i = 0; i < 4; i++)
                #pragma unroll
                for (int j = 0; j < 4; j++) {
                    sr[i][j] = fmaf(qr[i], kr[j], sr[i][j]);
                    sr[i][j] = fmaf(qi[i], ki[j], sr[i][j]);
                    si[i][j] = fmaf(qr[i], ki[j], si[i][j]);
                    si[i][j] = fmaf(-qi[i], kr[j], si[i][j]);
                }
        }
        __syncthreads();
    }

    const size_t base = (size_t)bh * QL * QL;
    #pragma unroll
    for (int i = 0; i < 4; i++) {
        const int q = q0 + ty * 4 + i;
        float4 v; v.x = sr[i][0]; v.y = sr[i][1]; v.z = sr[i][2]; v.w = sr[i][3];
        float4 w; w.x = si[i][0]; w.y = si[i][1]; w.z = si[i][2]; w.w = si[i][3];
        *(float4*)(g_Sr + base + (size_t)q * QL + k0 + tx * 4) = v;
        *(float4*)(g_Si + base + (size_t)q * QL + k0 + tx * 4) = w;
    }
}

// ---------------------------------------------------------------------------
// Row softmax stats: m = max_k s, il = 1/sum_k exp(s-m), s = (Sr^2+Si^2)/8
// One block (256 threads) per row; 32768 rows.
// ---------------------------------------------------------------------------
__global__ __launch_bounds__(256) void softmax_stats()
{
    const int row = blockIdx.x;
    const float* sr = g_Sr + (size_t)row * QL;
    const float* si = g_Si + (size_t)row * QL;
    const int tid = threadIdx.x;

    float sv[8];
    float mx = -3.4e38f;
    #pragma unroll
    for (int i = 0; i < 8; i++) {
        int k = i * 256 + tid;
        float a = sr[k], b = si[k];
        float s = (a * a + b * b) * 0.125f;
        sv[i] = s;
        mx = fmaxf(mx, s);
    }

    __shared__ float red[256];
    red[tid] = mx;
    __syncthreads();
    #pragma unroll
    for (int off = 128; off > 0; off >>= 1) {
        if (tid < off) red[tid] = fmaxf(red[tid], red[tid + off]);
        __syncthreads();
    }
    const float m = red[0];
    __syncthreads();

    float sum = 0.f;
    #pragma unroll
    for (int i = 0; i < 8; i++) sum += __expf(sv[i] - m);
    red[tid] = sum;
    __syncthreads();
    #pragma unroll
    for (int off = 128; off > 0; off >>= 1) {
        if (tid < off) red[tid] += red[tid + off];
        __syncthreads();
    }
    if (tid == 0) { g_m[row] = m; g_il[row] = 1.0f / red[0]; }
}

// ---------------------------------------------------------------------------
// AV: A = softmax(s); write A to output; ac = A*Sr/r, as = A*Si/r;
// Or += ac Vr - as Vi ; Oi += as Vr + ac Vi.  Block: 64 q-rows, full Dh=64,
// keys consumed in tiles of 32.
// ---------------------------------------------------------------------------
__global__ __launch_bounds__(256) void av_kernel(float* __restrict__ attn)
{
    __shared__ float acs[32][65], ass[32][65];
    __shared__ float vrs[32][64], vis[32][64];
    __shared__ float smM[64], smIl[64];

    const int bh = blockIdx.y;
    const int q0 = blockIdx.x * 64;
    const size_t sbase = (size_t)bh * QL * QL;
    const size_t hb = (size_t)bh * QL * QDh;
    const float* Vr = g_V + hb;
    const float* Vi = g_V + hb + RIOFF;

    const int tid = threadIdx.x;
    const int ty = tid >> 4, tx = tid & 15;

    if (tid < 64) {
        smM[tid]  = g_m[bh * QL + q0 + tid];
        smIl[tid] = g_il[bh * QL + q0 + tid];
    }
    __syncthreads();

    float orr[4][4], oii[4][4];
    #pragma unroll
    for (int i = 0; i < 4; i++)
        #pragma unroll
        for (int j = 0; j < 4; j++) { orr[i][j] = 0.f; oii[i][j] = 0.f; }

    for (int k0 = 0; k0 < QL; k0 += 32) {
        #pragma unroll
        for (int i = 0; i < 8; i++) {
            int idx = i * 256 + tid;
            int k = idx & 31, q = idx >> 5;
            size_t g = sbase + (size_t)(q0 + q) * QL + k0 + k;
            float a = g_Sr[g], b = g_Si[g];
            float r2 = a * a + b * b;
            float s = r2 * 0.125f;
            float A = __expf(s - smM[q]) * smIl[q];
            attn[g] = A;
            float inv = rsqrtf(r2);
            float cr = 1.f, sn = 0.f;
            if (r2 > 0.f) { cr = a * inv; sn = b * inv; }
            acs[k][q] = A * cr;
            ass[k][q] = A * sn;
        }
        #pragma unroll
        for (int i = 0; i < 8; i++) {
            int idx = i * 256 + tid;
            int kk = idx >> 6, dh = idx & 63;
            vrs[kk][dh] = Vr[(size_t)(k0 + kk) * QDh + dh];
            vis[kk][dh] = Vi[(size_t)(k0 + kk) * QDh + dh];
        }
        __syncthreads();
        #pragma unroll
        for (int kk = 0; kk < 32; kk++) {
            float ac[4], as4[4];
            #pragma unroll
            for (int i = 0; i < 4; i++) {
                ac[i]  = acs[kk][ty * 4 + i];
                as4[i] = ass[kk][ty * 4 + i];
            }
            float vr[4], vi4[4];
            *(float4*)vr  = *(const float4*)&vrs[kk][tx * 4];
            *(float4*)vi4 = *(const float4*)&vis[kk][tx * 4];
            #pragma unroll
            for (int i = 0; i < 4; i++)
                #pragma unroll
                for (int j = 0; j < 4; j++) {
                    orr[i][j] = fmaf(ac[i],   vr[j],  orr[i][j]);
                    orr[i][j] = fmaf(-as4[i], vi4[j], orr[i][j]);
                    oii[i][j] = fmaf(as4[i],  vr[j],  oii[i][j]);
                    oii[i][j] = fmaf(ac[i],   vi4[j], oii[i][j]);
                }
        }
        __syncthreads();
    }

    const int b = bh >> 3, h = bh & 7;
    #pragma unroll
    for (int i = 0; i < 4; i++) {
        int q = q0 + ty * 4 + i;
        size_t o = ((size_t)b * QL + q) * QD + h * QDh + tx * 4;
        float4 v; v.x = orr[i][0]; v.y = orr[i][1]; v.z = orr[i][2]; v.w = orr[i][3];
        float4 w; w.x = oii[i][0]; w.y = oii[i][1]; w.z = oii[i][2]; w.w = oii[i][3];
        *(float4*)(g_Or + o) = v;
        *(float4*)(g_Oi + o) = w;
    }
}

// ---------------------------------------------------------------------------

extern "C" void kernel_launch(void* const* d_in, const int* in_sizes, int n_in,
                              void* d_out, int out_size)
{
    const float* wr = (const float*)d_in[0];
    const float* wi = (const float*)d_in[1];
    const float* Wq = (const float*)d_in[2];
    const float* bq = (const float*)d_in[3];
    const float* Wk = (const float*)d_in[4];
    const float* bk = (const float*)d_in[5];
    const float* Wv = (const float*)d_in[6];
    const float* bv = (const float*)d_in[7];
    const float* Wo = (const float*)d_in[8];
    const float* bo = (const float*)d_in[9];

    float* out      = (float*)d_out;
    float* out_real = out;
    float* out_imag = out + (size_t)QB * QL * QD;
    float* attn     = out + (size_t)2 * QB * QL * QD;

    dim3 gProj(4, 64);   // N/128 x 8192/128
    dim3 gOut(4, 32);    // N/128 x 4096/128

    gemm128<0><<<gProj, 256>>>(wr, wi, Wq, bq, nullptr, 0);
    gemm128<0><<<gProj, 256>>>(wr, wi, Wk, bk, nullptr, 1);
    gemm128<0><<<gProj, 256>>>(wr, wi, Wv, bv, nullptr, 2);

    qk_kernel<<<dim3(32, 32, 16), 256>>>();
    softmax_stats<<<QBH * QL, 256>>>();
    av_kernel<<<dim3(32, 16), 256>>>(attn);

    gemm128<1><<<gOut, 256>>>(nullptr, nullptr, Wo, bo, out_real, 0);
    gemm128<1><<<gOut, 256>>>(nullptr, nullptr, Wo, bo, out_imag, 1);
}

// round 3
// speedup vs baseline: 1.0021x; 1.0021x over previous
#include <cuda_runtime.h>
#include <math.h>

// ---------------------------------------------------------------------------
// QuantumAttention: B=2, L=2048, D=512, H=8, Dh=64
// out = (out_real[B,L,D], out_imag[B,L,D], attention[B,H,L,L]) concatenated
// ---------------------------------------------------------------------------

namespace {
constexpr int QB = 2, QL = 2048, QD = 512, QH = 8, QDh = 64;
constexpr int QBH = QB * QH;                       // 16
constexpr size_t RIOFF = (size_t)QB * QH * QL * QDh;   // 2,097,152 (real/imag plane)
constexpr size_t QSZ   = 2 * RIOFF;                    // 4,194,304
constexpr size_t SSZ   = (size_t)QBH * QL * QL;        // 67,108,864
}

// Scratch (device globals: no runtime allocation allowed)
__device__ float g_Q[QSZ];
__device__ float g_K[QSZ];
__device__ float g_V[QSZ];
__device__ float g_Sr[SSZ];
__device__ float g_Si[SSZ];
__device__ float g_m[QBH * QL];
__device__ float g_il[QBH * QL];
__device__ float g_Or[(size_t)QB * QL * QD];
__device__ float g_Oi[(size_t)QB * QL * QD];

// ---------------------------------------------------------------------------
// GEMM: C[r,c] = sum_k X[r,k] * W[c,k] + bias[c], K = N = 512.
// MODE 0: X rows 0..4095 from X0 (wave_real), 4096..8191 from X1 (wave_imag);
//         output scattered to g_Q/g_K/g_V (sel) in [ri][b][h][l][dh] layout.
// MODE 1: X = g_Or (sel=0) / g_Oi (sel=1); output row-major to Yext.
// Block tile 128x128, K-tile 8, 256 threads, 8x8 per-thread micro-tile.
// ---------------------------------------------------------------------------
template <int MODE>
__global__ __launch_bounds__(256) void gemm128(
    const float* __restrict__ X0, const float* __restrict__ X1,
    const float* __restrict__ Wt, const float* __restrict__ bias,
    float* __restrict__ Yext, int sel)
{
    __shared__ float As[8][128];
    __shared__ float Bs[8][128];

    const int tid = threadIdx.x;
    const int r0 = blockIdx.y * 128;
    const int c0 = blockIdx.x * 128;

    const float* X;
    int rbase = r0;
    if (MODE == 0) {
        if (r0 >= 4096) { X = X1; rbase = r0 - 4096; }
        else            { X = X0; }
    } else {
        X = sel ? g_Oi : g_Or;
    }

    const int lr = tid >> 1;          // 0..127
    const int lc = (tid & 1) << 2;    // 0 or 4
    const int ty = tid >> 4;          // 0..15
    const int tx = tid & 15;          // 0..15

    float acc[8][8];
    #pragma unroll
    for (int i = 0; i < 8; i++)
        #pragma unroll
        for (int j = 0; j < 8; j++) acc[i][j] = 0.f;

    const float* Arow = X  + (size_t)(rbase + lr) * 512 + lc;
    const float* Brow = Wt + (size_t)(c0 + lr) * 512 + lc;

    for (int k0 = 0; k0 < 512; k0 += 8) {
        float4 a = *(const float4*)(Arow + k0);
        float4 b = *(const float4*)(Brow + k0);
        As[lc + 0][lr] = a.x; As[lc + 1][lr] = a.y;
        As[lc + 2][lr] = a.z; As[lc + 3][lr] = a.w;
        Bs[lc + 0][lr] = b.x; Bs[lc + 1][lr] = b.y;
        Bs[lc + 2][lr] = b.z; Bs[lc + 3][lr] = b.w;
        __syncthreads();
        #pragma unroll
        for (int k = 0; k < 8; k++) {
            float av[8], bv[8];
            *(float4*)&av[0] = *(const float4*)&As[k][ty * 8];
            *(float4*)&av[4] = *(const float4*)&As[k][ty * 8 + 4];
            *(float4*)&bv[0] = *(const float4*)&Bs[k][tx * 8];
            *(float4*)&bv[4] = *(const float4*)&Bs[k][tx * 8 + 4];
            #pragma unroll
            for (int i = 0; i < 8; i++)
                #pragma unroll
                for (int j = 0; j < 8; j++)
                    acc[i][j] = fmaf(av[i], bv[j], acc[i][j]);
        }
        __syncthreads();
    }

    #pragma unroll
    for (int i = 0; i < 8; i++) {
        const int r = r0 + ty * 8 + i;
        #pragma unroll
        for (int j = 0; j < 8; j++) {
            const int c = c0 + tx * 8 + j;
            float v = acc[i][j] + bias[c];
            if (MODE == 0) {
                const int ri = r >> 12;
                const int bl = r & 4095;
                const int bb = bl >> 11;
                const int l  = bl & 2047;
                const int h  = c >> 6;
                const int dh = c & 63;
                size_t idx = ((((size_t)ri * QB + bb) * QH + h) * QL + l) * QDh + dh;
                float* dst = (sel == 0) ? g_Q : (sel == 1) ? g_K : g_V;
                dst[idx] = v;
            } else {
                Yext[(size_t)r * 512 + c] = v;
            }
        }
    }
}

// ---------------------------------------------------------------------------
// QK: Sr = Qr Kr^T + Qi Ki^T ; Si = Qr Ki^T - Qi Kr^T, per (b,h).
// Block: 64 q-rows x 64 k-cols, full Dh=64 in 4 chunks of 16.
// ---------------------------------------------------------------------------
__global__ __launch_bounds__(256) void qk_kernel()
{
    __shared__ float Qrs[16][68], Qis[16][68], Krs[16][68], Kis[16][68];

    const int bh = blockIdx.z;
    const int q0 = blockIdx.y * 64;
    const int k0 = blockIdx.x * 64;
    const size_t hb = (size_t)bh * QL * QDh;
    const float* Qr = g_Q + hb;
    const float* Qi = g_Q + hb + RIOFF;
    const float* Kr = g_K + hb;
    const float* Ki = g_K + hb + RIOFF;

    const int tid = threadIdx.x;
    const int lr = tid >> 2;          // 0..63
    const int lc = (tid & 3) << 2;    // 0,4,8,12
    const int ty = tid >> 4;          // 0..15
    const int tx = tid & 15;          // 0..15

    float sr[4][4], si[4][4];
    #pragma unroll
    for (int i = 0; i < 4; i++)
        #pragma unroll
        for (int j = 0; j < 4; j++) { sr[i][j] = 0.f; si[i][j] = 0.f; }

    for (int d0 = 0; d0 < 64; d0 += 16) {
        float4 aqr = *(const float4*)(Qr + (size_t)(q0 + lr) * QDh + d0 + lc);
        float4 aqi = *(const float4*)(Qi + (size_t)(q0 + lr) * QDh + d0 + lc);
        float4 akr = *(const float4*)(Kr + (size_t)(k0 + lr) * QDh + d0 + lc);
        float4 aki = *(const float4*)(Ki + (size_t)(k0 + lr) * QDh + d0 + lc);
        Qrs[lc + 0][lr] = aqr.x; Qrs[lc + 1][lr] = aqr.y;
        Qrs[lc + 2][lr] = aqr.z; Qrs[lc + 3][lr] = aqr.w;
        Qis[lc + 0][lr] = aqi.x; Qis[lc + 1][lr] = aqi.y;
        Qis[lc + 2][lr] = aqi.z; Qis[lc + 3][lr] = aqi.w;
        Krs[lc + 0][lr] = akr.x; Krs[lc + 1][lr] = akr.y;
        Krs[lc + 2][lr] = akr.z; Krs[lc + 3][lr] = akr.w;
        Kis[lc + 0][lr] = aki.x; Kis[lc + 1][lr] = aki.y;
        Kis[lc + 2][lr] = aki.z; Kis[lc + 3][lr] = aki.w;
        __syncthreads();
        #pragma unroll
        for (int kk = 0; kk < 16; kk++) {
            float qr[4], qi[4], kr[4], ki[4];
            *(float4*)qr = *(const float4*)&Qrs[kk][ty * 4];
            *(float4*)qi = *(const float4*)&Qis[kk][ty * 4];
            *(float4*)kr = *(const float4*)&Krs[kk][tx * 4];
            *(float4*)ki = *(const float4*)&Kis[kk][tx * 4];
            #pragma unroll
            for (int i = 0; i < 4; i++)
                #pragma unroll
                for (int j = 0; j < 4; j++) {
                    sr[i][j] = fmaf(qr[i], kr[j], sr[i][j]);
                    sr[i][j] = fmaf(qi[i], ki[j], sr[i][j]);
                    si[i][j] = fmaf(qr[i], ki[j], si[i][j]);
                    si[i][j] = fmaf(-qi[i], kr[j], si[i][j]);
                }
        }
        __syncthreads();
    }

    const size_t base = (size_t)bh * QL * QL;
    #pragma unroll
    for (int i = 0; i < 4; i++) {
        const int q = q0 + ty * 4 + i;
        float4 v; v.x = sr[i][0]; v.y = sr[i][1]; v.z = sr[i][2]; v.w = sr[i][3];
        float4 w; w.x = si[i][0]; w.y = si[i][1]; w.z = si[i][2]; w.w = si[i][3];
        *(float4*)(g_Sr + base + (size_t)q * QL + k0 + tx * 4) = v;
        *(float4*)(g_Si + base + (size_t)q * QL + k0 + tx * 4) = w;
    }
}

// ---------------------------------------------------------------------------
// Row softmax stats: m = max_k s, il = 1/sum_k exp(s-m), s = (Sr^2+Si^2)/8
// One block (256 threads) per row; 32768 rows.
// ---------------------------------------------------------------------------
__global__ __launch_bounds__(256) void softmax_stats()
{
    const int row = blockIdx.x;
    const float* sr = g_Sr + (size_t)row * QL;
    const float* si = g_Si + (size_t)row * QL;
    const int tid = threadIdx.x;

    float sv[8];
    float mx = -3.4e38f;
    #pragma unroll
    for (int i = 0; i < 8; i++) {
        int k = i * 256 + tid;
        float a = sr[k], b = si[k];
        float s = (a * a + b * b) * 0.125f;
        sv[i] = s;
        mx = fmaxf(mx, s);
    }

    __shared__ float red[256];
    red[tid] = mx;
    __syncthreads();
    #pragma unroll
    for (int off = 128; off > 0; off >>= 1) {
        if (tid < off) red[tid] = fmaxf(red[tid], red[tid + off]);
        __syncthreads();
    }
    const float m = red[0];
    __syncthreads();

    float sum = 0.f;
    #pragma unroll
    for (int i = 0; i < 8; i++) sum += __expf(sv[i] - m);
    red[tid] = sum;
    __syncthreads();
    #pragma unroll
    for (int off = 128; off > 0; off >>= 1) {
        if (tid < off) red[tid] += red[tid + off];
        __syncthreads();
    }
    if (tid == 0) { g_m[row] = m; g_il[row] = 1.0f / red[0]; }
}

// ---------------------------------------------------------------------------
// AV: A = softmax(s); write A to output; ac = A*Sr/r, as = A*Si/r;
// Or += ac Vr - as Vi ; Oi += as Vr + ac Vi.  Block: 64 q-rows, full Dh=64,
// keys consumed in tiles of 32.
// ---------------------------------------------------------------------------
__global__ __launch_bounds__(256) void av_kernel(float* __restrict__ attn)
{
    __shared__ float acs[32][65], ass[32][65];
    __shared__ float vrs[32][64], vis[32][64];
    __shared__ float smM[64], smIl[64];

    const int bh = blockIdx.y;
    const int q0 = blockIdx.x * 64;
    const size_t sbase = (size_t)bh * QL * QL;
    const size_t hb = (size_t)bh * QL * QDh;
    const float* Vr = g_V + hb;
    const float* Vi = g_V + hb + RIOFF;

    const int tid = threadIdx.x;
    const int ty = tid >> 4, tx = tid & 15;

    if (tid < 64) {
        smM[tid]  = g_m[bh * QL + q0 + tid];
        smIl[tid] = g_il[bh * QL + q0 + tid];
    }
    __syncthreads();

    float orr[4][4], oii[4][4];
    #pragma unroll
    for (int i = 0; i < 4; i++)
        #pragma unroll
        for (int j = 0; j < 4; j++) { orr[i][j] = 0.f; oii[i][j] = 0.f; }

    for (int k0 = 0; k0 < QL; k0 += 32) {
        #pragma unroll
        for (int i = 0; i < 8; i++) {
            int idx = i * 256 + tid;
            int k = idx & 31, q = idx >> 5;
            size_t g = sbase + (size_t)(q0 + q) * QL + k0 + k;
            float a = g_Sr[g], b = g_Si[g];
            float r2 = a * a + b * b;
            float s = r2 * 0.125f;
            float A = __expf(s - smM[q]) * smIl[q];
            attn[g] = A;
            float inv = rsqrtf(r2);
            float cr = 1.f, sn = 0.f;
            if (r2 > 0.f) { cr = a * inv; sn = b * inv; }
            acs[k][q] = A * cr;
            ass[k][q] = A * sn;
        }
        #pragma unroll
        for (int i = 0; i < 8; i++) {
            int idx = i * 256 + tid;
            int kk = idx >> 6, dh = idx & 63;
            vrs[kk][dh] = Vr[(size_t)(k0 + kk) * QDh + dh];
            vis[kk][dh] = Vi[(size_t)(k0 + kk) * QDh + dh];
        }
        __syncthreads();
        #pragma unroll
        for (int kk = 0; kk < 32; kk++) {
            float ac[4], as4[4];
            #pragma unroll
            for (int i = 0; i < 4; i++) {
                ac[i]  = acs[kk][ty * 4 + i];
                as4[i] = ass[kk][ty * 4 + i];
            }
            float vr[4], vi4[4];
            *(float4*)vr  = *(const float4*)&vrs[kk][tx * 4];
            *(float4*)vi4 = *(const float4*)&vis[kk][tx * 4];
            #pragma unroll
            for (int i = 0; i < 4; i++)
                #pragma unroll
                for (int j = 0; j < 4; j++) {
                    orr[i][j] = fmaf(ac[i],   vr[j],  orr[i][j]);
                    orr[i][j] = fmaf(-as4[i], vi4[j], orr[i][j]);
                    oii[i][j] = fmaf(as4[i],  vr[j],  oii[i][j]);
                    oii[i][j] = fmaf(ac[i],   vi4[j], oii[i][j]);
                }
        }
        __syncthreads();
    }

    const int b = bh >> 3, h = bh & 7;
    #pragma unroll
    for (int i = 0; i < 4; i++) {
        int q = q0 + ty * 4 + i;
        size_t o = ((size_t)b * QL + q) * QD + h * QDh + tx * 4;
        float4 v; v.x = orr[i][0]; v.y = orr[i][1]; v.z = orr[i][2]; v.w = orr[i][3];
        float4 w; w.x = oii[i][0]; w.y = oii[i][1]; w.z = oii[i][2]; w.w = oii[i][3];
        *(float4*)(g_Or + o) = v;
        *(float4*)(g_Oi + o) = w;
    }
}

// ---------------------------------------------------------------------------

extern "C" void kernel_launch(void* const* d_in, const int* in_sizes, int n_in,
                              void* d_out, int out_size)
{
    const float* wr = (const float*)d_in[0];
    const float* wi = (const float*)d_in[1];
    const float* Wq = (const float*)d_in[2];
    const float* bq = (const float*)d_in[3];
    const float* Wk = (const float*)d_in[4];
    const float* bk = (const float*)d_in[5];
    const float* Wv = (const float*)d_in[6];
    const float* bv = (const float*)d_in[7];
    const float* Wo = (const float*)d_in[8];
    const float* bo = (const float*)d_in[9];

    float* out      = (float*)d_out;
    float* out_real = out;
    float* out_imag = out + (size_t)QB * QL * QD;
    float* attn     = out + (size_t)2 * QB * QL * QD;

    dim3 gProj(4, 64);   // N/128 x 8192/128
    dim3 gOut(4, 32);    // N/128 x 4096/128

    gemm128<0><<<gProj, 256>>>(wr, wi, Wq, bq, nullptr, 0);
    gemm128<0><<<gProj, 256>>>(wr, wi, Wk, bk, nullptr, 1);
    gemm128<0><<<gProj, 256>>>(wr, wi, Wv, bv, nullptr, 2);

    qk_kernel<<<dim3(32, 32, 16), 256>>>();
    softmax_stats<<<QBH * QL, 256>>>();
    av_kernel<<<dim3(32, 16), 256>>>(attn);

    gemm128<1><<<gOut, 256>>>(nullptr, nullptr, Wo, bo, out_real, 0);
    gemm128<1><<<gOut, 256>>>(nullptr, nullptr, Wo, bo, out_imag, 1);
}

// round 5
// speedup vs baseline: 1.1684x; 1.1660x over previous
#include <cuda_runtime.h>
#include <math.h>
#include <stdint.h>

namespace {
constexpr int QB = 2, QL = 2048, QD = 512, QH = 8, QDh = 64;
constexpr int QBH = QB * QH;
constexpr size_t RIOFF = (size_t)QBH * QL * QDh;
constexpr size_t QSZ   = 2 * RIOFF;
constexpr size_t SSZ   = (size_t)QBH * QL * QL;
}

__device__ uint32_t g_Qh[QSZ], g_Ql[QSZ];
__device__ uint32_t g_Kh[QSZ], g_Kl[QSZ];
__device__ uint32_t g_Vh[QSZ], g_Vl[QSZ];
__device__ float g_Sr[SSZ], g_Si[SSZ];
__device__ float g_m[QBH * QL], g_il[QBH * QL];
__device__ float g_Or[(size_t)QB * QL * QD], g_Oi[(size_t)QB * QL * QD];

__device__ __forceinline__ uint32_t tf32h(float x) {
    uint32_t u; asm("cvt.rna.tf32.f32 %0, %1;" : "=r"(u) : "f"(x)); return u;
}
__device__ __forceinline__ void f2tf(float x, uint32_t& h, uint32_t& l) {
    h = tf32h(x);
    l = tf32h(x - __uint_as_float(h));
}
__device__ __forceinline__ void mma8(float c[4], const uint32_t a[4],
                                     uint32_t b0, uint32_t b1) {
    asm volatile(
        "mma.sync.aligned.m16n8k8.row.col.f32.tf32.tf32.f32 "
        "{%0,%1,%2,%3},{%4,%5,%6,%7},{%8,%9},{%0,%1,%2,%3};"
        : "+f"(c[0]), "+f"(c[1]), "+f"(c[2]), "+f"(c[3])
        : "r"(a[0]), "r"(a[1]), "r"(a[2]), "r"(a[3]), "r"(b0), "r"(b1));
}

// ---------------------------------------------------------------------------
// Projections (SIMT fp32). MODE 0: writes tf32 hi/lo planes of Q/K/V.
// MODE 1: output projection, row-major float out.
// ---------------------------------------------------------------------------
template <int MODE>
__global__ __launch_bounds__(256) void gemm128(
    const float* __restrict__ X0, const float* __restrict__ X1,
    const float* __restrict__ Wt, const float* __restrict__ bias,
    float* __restrict__ Yext, int sel)
{
    __shared__ float As[8][128];
    __shared__ float Bs[8][128];

    const int tid = threadIdx.x;
    const int r0 = blockIdx.y * 128;
    const int c0 = blockIdx.x * 128;

    const float* X;
    int rbase = r0;
    if (MODE == 0) {
        if (r0 >= 4096) { X = X1; rbase = r0 - 4096; }
        else            { X = X0; }
    } else {
        X = sel ? g_Oi : g_Or;
    }

    const int lr = tid >> 1, lc = (tid & 1) << 2;
    const int ty = tid >> 4, tx = tid & 15;

    float acc[8][8];
    #pragma unroll
    for (int i = 0; i < 8; i++)
        #pragma unroll
        for (int j = 0; j < 8; j++) acc[i][j] = 0.f;

    const float* Arow = X  + (size_t)(rbase + lr) * 512 + lc;
    const float* Brow = Wt + (size_t)(c0 + lr) * 512 + lc;

    for (int k0 = 0; k0 < 512; k0 += 8) {
        float4 a = *(const float4*)(Arow + k0);
        float4 b = *(const float4*)(Brow + k0);
        As[lc + 0][lr] = a.x; As[lc + 1][lr] = a.y;
        As[lc + 2][lr] = a.z; As[lc + 3][lr] = a.w;
        Bs[lc + 0][lr] = b.x; Bs[lc + 1][lr] = b.y;
        Bs[lc + 2][lr] = b.z; Bs[lc + 3][lr] = b.w;
        __syncthreads();
        #pragma unroll
        for (int k = 0; k < 8; k++) {
            float av[8], bv[8];
            *(float4*)&av[0] = *(const float4*)&As[k][ty * 8];
            *(float4*)&av[4] = *(const float4*)&As[k][ty * 8 + 4];
            *(float4*)&bv[0] = *(const float4*)&Bs[k][tx * 8];
            *(float4*)&bv[4] = *(const float4*)&Bs[k][tx * 8 + 4];
            #pragma unroll
            for (int i = 0; i < 8; i++)
                #pragma unroll
                for (int j = 0; j < 8; j++)
                    acc[i][j] = fmaf(av[i], bv[j], acc[i][j]);
        }
        __syncthreads();
    }

    #pragma unroll
    for (int i = 0; i < 8; i++) {
        const int r = r0 + ty * 8 + i;
        #pragma unroll
        for (int j = 0; j < 8; j++) {
            const int c = c0 + tx * 8 + j;
            float v = acc[i][j] + bias[c];
            if (MODE == 0) {
                const int ri = r >> 12;
                const int bl = r & 4095;
                const int bb = bl >> 11;
                const int l  = bl & 2047;
                const int h  = c >> 6;
                const int dh = c & 63;
                size_t idx = ((((size_t)ri * QB + bb) * QH + h) * QL + l) * QDh + dh;
                uint32_t* dH = (sel == 0) ? g_Qh : (sel == 1) ? g_Kh : g_Vh;
                uint32_t* dL = (sel == 0) ? g_Ql : (sel == 1) ? g_Kl : g_Vl;
                uint32_t hh, ll; f2tf(v, hh, ll);
                dH[idx] = hh; dL[idx] = ll;
            } else {
                Yext[(size_t)r * 512 + c] = v;
            }
        }
    }
}

// ---------------------------------------------------------------------------
// QK on tensor cores. Block: 128 q x 64 n, 8 warps (warp tile 16x64).
// Sr = QrKr + QiKi ; Si = QrKi + (-Qi)Kr.  Split-tf32, 3 passes/product.
// ---------------------------------------------------------------------------
__global__ __launch_bounds__(256) void qk_mma()
{
    __shared__ uint32_t sB[4][32 * 72];   // KrH,KrL,KiH,KiL  [dh][n] pitch 72

    const int bh = blockIdx.z;
    const int q0 = blockIdx.y * 128;
    const int n0 = blockIdx.x * 64;
    const int tid = threadIdx.x;
    const int warp = tid >> 5, lane = tid & 31;
    const int g = lane >> 2, t = lane & 3;
    const int qw = q0 + warp * 16;

    const size_t hb = (size_t)bh * QL * QDh;
    const uint32_t* QrH = g_Qh + hb;
    const uint32_t* QrL = g_Ql + hb;
    const uint32_t* QiH = g_Qh + RIOFF + hb;
    const uint32_t* QiL = g_Ql + RIOFF + hb;
    const uint32_t* Ks[4] = { g_Kh + hb, g_Kl + hb,
                              g_Kh + RIOFF + hb, g_Kl + RIOFF + hb };

    float Sr[8][4], Si[8][4];
    #pragma unroll
    for (int i = 0; i < 8; i++)
        #pragma unroll
        for (int j = 0; j < 4; j++) { Sr[i][j] = 0.f; Si[i][j] = 0.f; }

    #pragma unroll
    for (int kc = 0; kc < 2; ++kc) {
        __syncthreads();
        #pragma unroll
        for (int it = 0; it < 2; ++it) {
            int s = tid + it * 256;
            int n = s & 63, dg = s >> 6;    // dg: 0..7 -> 4 dh rows each
            #pragma unroll
            for (int p = 0; p < 4; p++) {
                uint4 v = *(const uint4*)(Ks[p] + (size_t)(n0 + n) * QDh + kc * 32 + dg * 4);
                sB[p][(dg * 4 + 0) * 72 + n] = v.x;
                sB[p][(dg * 4 + 1) * 72 + n] = v.y;
                sB[p][(dg * 4 + 2) * 72 + n] = v.z;
                sB[p][(dg * 4 + 3) * 72 + n] = v.w;
            }
        }
        __syncthreads();

        #pragma unroll
        for (int ks = 0; ks < 4; ++ks) {
            const int kd = kc * 32 + ks * 8 + t;
            const size_t ra = (size_t)(qw + g) * QDh + kd;
            const size_t rb = ra + (size_t)8 * QDh;
            uint32_t qrh[4] = { QrH[ra], QrH[rb], QrH[ra + 4], QrH[rb + 4] };
            uint32_t qrl[4] = { QrL[ra], QrL[rb], QrL[ra + 4], QrL[rb + 4] };
            uint32_t qih[4] = { QiH[ra], QiH[rb], QiH[ra + 4], QiH[rb + 4] };
            uint32_t qil[4] = { QiL[ra], QiL[rb], QiL[ra + 4], QiL[rb + 4] };
            uint32_t nih[4], nil_[4];
            #pragma unroll
            for (int e = 0; e < 4; e++) {
                nih[e]  = qih[e] ^ 0x80000000u;
                nil_[e] = qil[e] ^ 0x80000000u;
            }
            const int rr1 = (ks * 8 + t) * 72, rr2 = (ks * 8 + t + 4) * 72;
            #pragma unroll
            for (int nt = 0; nt < 8; ++nt) {
                const int cb = nt * 8 + g;
                uint32_t krh0 = sB[0][rr1 + cb], krh1 = sB[0][rr2 + cb];
                uint32_t krl0 = sB[1][rr1 + cb], krl1 = sB[1][rr2 + cb];
                uint32_t kih0 = sB[2][rr1 + cb], kih1 = sB[2][rr2 + cb];
                uint32_t kil0 = sB[3][rr1 + cb], kil1 = sB[3][rr2 + cb];
                mma8(Sr[nt], qrh, krh0, krh1);
                mma8(Sr[nt], qrh, krl0, krl1);
                mma8(Sr[nt], qrl, krh0, krh1);
                mma8(Sr[nt], qih, kih0, kih1);
                mma8(Sr[nt], qih, kil0, kil1);
                mma8(Sr[nt], qil, kih0, kih1);
                mma8(Si[nt], qrh, kih0, kih1);
                mma8(Si[nt], qrh, kil0, kil1);
                mma8(Si[nt], qrl, kih0, kih1);
                mma8(Si[nt], nih, krh0, krh1);
                mma8(Si[nt], nih, krl0, krl1);
                mma8(Si[nt], nil_, krh0, krh1);
            }
        }
    }

    const size_t base = (size_t)bh * QL * QL;
    #pragma unroll
    for (int nt = 0; nt < 8; ++nt) {
        const int col = n0 + nt * 8 + 2 * t;
        size_t o0 = base + (size_t)(qw + g) * QL + col;
        size_t o1 = base + (size_t)(qw + g + 8) * QL + col;
        *(float2*)(g_Sr + o0) = make_float2(Sr[nt][0], Sr[nt][1]);
        *(float2*)(g_Si + o0) = make_float2(Si[nt][0], Si[nt][1]);
        *(float2*)(g_Sr + o1) = make_float2(Sr[nt][2], Sr[nt][3]);
        *(float2*)(g_Si + o1) = make_float2(Si[nt][2], Si[nt][3]);
    }
}

// ---------------------------------------------------------------------------
// Row softmax stats.
// ---------------------------------------------------------------------------
__global__ __launch_bounds__(256) void softmax_stats()
{
    const int row = blockIdx.x;
    const float* sr = g_Sr + (size_t)row * QL;
    const float* si = g_Si + (size_t)row * QL;
    const int tid = threadIdx.x;

    float sv[8];
    float mx = -3.4e38f;
    #pragma unroll
    for (int i = 0; i < 8; i++) {
        int k = i * 256 + tid;
        float a = sr[k], b = si[k];
        float s = (a * a + b * b) * 0.125f;
        sv[i] = s;
        mx = fmaxf(mx, s);
    }

    __shared__ float red[256];
    red[tid] = mx;
    __syncthreads();
    #pragma unroll
    for (int off = 128; off > 0; off >>= 1) {
        if (tid < off) red[tid] = fmaxf(red[tid], red[tid + off]);
        __syncthreads();
    }
    const float m = red[0];
    __syncthreads();

    float sum = 0.f;
    #pragma unroll
    for (int i = 0; i < 8; i++) sum += __expf(sv[i] - m);
    red[tid] = sum;
    __syncthreads();
    #pragma unroll
    for (int off = 128; off > 0; off >>= 1) {
        if (tid < off) red[tid] += red[tid + off];
        __syncthreads();
    }
    if (tid == 0) { g_m[row] = m; g_il[row] = 1.0f / red[0]; }
}

// ---------------------------------------------------------------------------
// AV on tensor cores. Block: 64 q rows x Dh=64; 8 warps = 4 q-warps x 2 n-warps
// (warp tile 16q x 32dh). ac/as computed per-thread in A-fragment positions.
// Or = ac*Vr + (-as)*Vi ; Oi = as*Vr + ac*Vi.  Split-tf32, 3 passes.
// ---------------------------------------------------------------------------
__global__ __launch_bounds__(256) void av_mma(float* __restrict__ attn)
{
    __shared__ uint32_t sV[4][32 * 72];   // VrH,VrL,ViH,ViL  [j][dh] pitch 72

    const int bh = blockIdx.y;
    const int q0 = blockIdx.x * 64;
    const int tid = threadIdx.x;
    const int warp = tid >> 5, lane = tid & 31;
    const int wq = warp >> 1, wn = warp & 1;
    const int g = lane >> 2, t = lane & 3;
    const int qw = q0 + wq * 16;
    const int r0 = qw + g, r1 = r0 + 8;

    const size_t hb = (size_t)bh * QL * QDh;
    const uint32_t* Vp[4] = { g_Vh + hb, g_Vl + hb,
                              g_Vh + RIOFF + hb, g_Vl + RIOFF + hb };

    const size_t sbase = (size_t)bh * QL * QL;
    const float* Sr0 = g_Sr + sbase + (size_t)r0 * QL;
    const float* Sr1 = g_Sr + sbase + (size_t)r1 * QL;
    const float* Si0 = g_Si + sbase + (size_t)r0 * QL;
    const float* Si1 = g_Si + sbase + (size_t)r1 * QL;
    const float m0 = g_m[bh * QL + r0],  m1 = g_m[bh * QL + r1];
    const float il0 = g_il[bh * QL + r0], il1 = g_il[bh * QL + r1];

    float Or[4][4], Oi[4][4];
    #pragma unroll
    for (int i = 0; i < 4; i++)
        #pragma unroll
        for (int j = 0; j < 4; j++) { Or[i][j] = 0.f; Oi[i][j] = 0.f; }

    for (int k0 = 0; k0 < QL; k0 += 32) {
        __syncthreads();
        #pragma unroll
        for (int it = 0; it < 2; ++it) {
            int idx = tid + it * 256;
            int jl = idx >> 4, dq = (idx & 15) * 4;
            #pragma unroll
            for (int p = 0; p < 4; p++) {
                uint4 v = *(const uint4*)(Vp[p] + (size_t)(k0 + jl) * QDh + dq);
                sV[p][jl * 72 + dq + 0] = v.x;
                sV[p][jl * 72 + dq + 1] = v.y;
                sV[p][jl * 72 + dq + 2] = v.z;
                sV[p][jl * 72 + dq + 3] = v.w;
            }
        }
        __syncthreads();

        #pragma unroll
        for (int ks = 0; ks < 4; ++ks) {
            uint32_t ach[4], acl[4], ash[4], asl[4], nsh[4], nsl[4];
            #pragma unroll
            for (int e = 0; e < 4; ++e) {
                const int j = k0 + ks * 8 + t + (e >> 1) * 4;
                const bool hi = e & 1;
                float a = hi ? Sr1[j] : Sr0[j];
                float b = hi ? Si1[j] : Si0[j];
                float r2 = a * a + b * b;
                float A = __expf(r2 * 0.125f - (hi ? m1 : m0)) * (hi ? il1 : il0);
                if (wn == 0)
                    attn[sbase + (size_t)(hi ? r1 : r0) * QL + j] = A;
                float cr, sn;
                if (r2 > 0.f) {
                    float inv = rsqrtf(r2);
                    cr = a * inv; sn = b * inv;
                } else { cr = 1.f; sn = 0.f; }
                f2tf(A * cr, ach[e], acl[e]);
                f2tf(A * sn, ash[e], asl[e]);
                nsh[e] = ash[e] ^ 0x80000000u;
                nsl[e] = asl[e] ^ 0x80000000u;
            }
            const int rr1 = (ks * 8 + t) * 72, rr2 = (ks * 8 + t + 4) * 72;
            #pragma unroll
            for (int nt = 0; nt < 4; ++nt) {
                const int cb = wn * 32 + nt * 8 + g;
                uint32_t vrh0 = sV[0][rr1 + cb], vrh1 = sV[0][rr2 + cb];
                uint32_t vrl0 = sV[1][rr1 + cb], vrl1 = sV[1][rr2 + cb];
                uint32_t vih0 = sV[2][rr1 + cb], vih1 = sV[2][rr2 + cb];
                uint32_t vil0 = sV[3][rr1 + cb], vil1 = sV[3][rr2 + cb];
                mma8(Or[nt], ach, vrh0, vrh1);
                mma8(Or[nt], ach, vrl0, vrl1);
                mma8(Or[nt], acl, vrh0, vrh1);
                mma8(Or[nt], nsh, vih0, vih1);
                mma8(Or[nt], nsh, vil0, vil1);
                mma8(Or[nt], nsl, vih0, vih1);
                mma8(Oi[nt], ash, vrh0, vrh1);
                mma8(Oi[nt], ash, vrl0, vrl1);
                mma8(Oi[nt], asl, vrh0, vrh1);
                mma8(Oi[nt], ach, vih0, vih1);
                mma8(Oi[nt], ach, vil0, vil1);
                mma8(Oi[nt], acl, vih0, vih1);
            }
        }
    }

    const int b = bh >> 3, h = bh & 7;
    #pragma unroll
    for (int nt = 0; nt < 4; ++nt) {
        const int dh = wn * 32 + nt * 8 + 2 * t;
        size_t o0 = ((size_t)b * QL + r0) * QD + h * QDh + dh;
        size_t o1 = ((size_t)b * QL + r1) * QD + h * QDh + dh;
        *(float2*)(g_Or + o0) = make_float2(Or[nt][0], Or[nt][1]);
        *(float2*)(g_Oi + o0) = make_float2(Oi[nt][0], Oi[nt][1]);
        *(float2*)(g_Or + o1) = make_float2(Or[nt][2], Or[nt][3]);
        *(float2*)(g_Oi + o1) = make_float2(Oi[nt][2], Oi[nt][3]);
    }
}

// ---------------------------------------------------------------------------

extern "C" void kernel_launch(void* const* d_in, const int* in_sizes, int n_in,
                              void* d_out, int out_size)
{
    const float* wr = (const float*)d_in[0];
    const float* wi = (const float*)d_in[1];
    const float* Wq = (const float*)d_in[2];
    const float* bq = (const float*)d_in[3];
    const float* Wk = (const float*)d_in[4];
    const float* bk = (const float*)d_in[5];
    const float* Wv = (const float*)d_in[6];
    const float* bv = (const float*)d_in[7];
    const float* Wo = (const float*)d_in[8];
    const float* bo = (const float*)d_in[9];

    float* out      = (float*)d_out;
    float* out_real = out;
    float* out_imag = out + (size_t)QB * QL * QD;
    float* attn     = out + (size_t)2 * QB * QL * QD;

    dim3 gProj(4, 64);
    dim3 gOut(4, 32);

    gemm128<0><<<gProj, 256>>>(wr, wi, Wq, bq, nullptr, 0);
    gemm128<0><<<gProj, 256>>>(wr, wi, Wk, bk, nullptr, 1);
    gemm128<0><<<gProj, 256>>>(wr, wi, Wv, bv, nullptr, 2);

    qk_mma<<<dim3(32, 16, 16), 256>>>();
    softmax_stats<<<QBH * QL, 256>>>();
    av_mma<<<dim3(32, 16), 256>>>(attn);

    gemm128<1><<<gOut, 256>>>(nullptr, nullptr, Wo, bo, out_real, 0);
    gemm128<1><<<gOut, 256>>>(nullptr, nullptr, Wo, bo, out_imag, 1);
}

// round 7
// speedup vs baseline: 1.4513x; 1.2421x over previous
#include <cuda_runtime.h>
#include <math.h>
#include <stdint.h>

namespace {
constexpr int QB = 2, QL = 2048, QD = 512, QH = 8, QDh = 64;
constexpr int QBH = QB * QH;
constexpr size_t RIOFF = (size_t)QBH * QL * QDh;
constexpr size_t QSZ   = 2 * RIOFF;
constexpr size_t SSZ   = (size_t)QBH * QL * QL;
}

__device__ uint32_t g_Qh[QSZ], g_Ql[QSZ];
__device__ uint32_t g_Kh[QSZ], g_Kl[QSZ];
__device__ uint32_t g_Vh[QSZ], g_Vl[QSZ];
__device__ float g_Sr[SSZ], g_Si[SSZ];   // after phase_kernel: Pc, Ps
__device__ float g_Or[(size_t)QB * QL * QD], g_Oi[(size_t)QB * QL * QD];

__device__ __forceinline__ uint32_t tf32h(float x) {
    uint32_t u; asm("cvt.rna.tf32.f32 %0, %1;" : "=r"(u) : "f"(x)); return u;
}
__device__ __forceinline__ void f2tf(float x, uint32_t& h, uint32_t& l) {
    h = tf32h(x);
    l = tf32h(x - __uint_as_float(h));
}
__device__ __forceinline__ void mma8(float c[4], const uint32_t a[4],
                                     uint32_t b0, uint32_t b1) {
    asm volatile(
        "mma.sync.aligned.m16n8k8.row.col.f32.tf32.tf32.f32 "
        "{%0,%1,%2,%3},{%4,%5,%6,%7},{%8,%9},{%0,%1,%2,%3};"
        : "+f"(c[0]), "+f"(c[1]), "+f"(c[2]), "+f"(c[3])
        : "r"(a[0]), "r"(a[1]), "r"(a[2]), "r"(a[3]), "r"(b0), "r"(b1));
}

// exp(x) for x <= 0, FMA-pipe only (no MUFU). ~1e-7 relative accuracy.
__device__ __forceinline__ float exp_neg_fast(float x) {
    const float LOG2E = 1.4426950408889634f;
    float t = x * LOG2E;                    // <= 0
    float fl = floorf(t);
    float r = t - fl;                       // [0,1)
    float y = r * 0.6931471805599453f;      // [0, ln2)
    // exp(y), Taylor degree 8 (rel err ~1e-7 on [0, ln2))
    float p = 2.4801587301587301e-5f;
    p = fmaf(p, y, 1.9841269841269841e-4f);
    p = fmaf(p, y, 1.3888888888888889e-3f);
    p = fmaf(p, y, 8.3333333333333333e-3f);
    p = fmaf(p, y, 4.1666666666666664e-2f);
    p = fmaf(p, y, 1.6666666666666666e-1f);
    p = fmaf(p, y, 5.0e-1f);
    p = fmaf(p, y, 1.0f);
    p = fmaf(p, y, 1.0f);
    int ni = (int)fl;
    ni = (ni < -127) ? -127 : ni;           // underflow -> scale 0
    float sc = __int_as_float((uint32_t)(ni + 127) << 23);
    return p * sc;
}

// rsqrt for r2 > 0, FMA-pipe only. ~1e-7 relative after 2 Newton steps.
__device__ __forceinline__ float rsqrt_fast(float x) {
    float y = __int_as_float(0x5f375a86u - (__float_as_uint(x) >> 1));
    y = y * fmaf(-0.5f * x, y * y, 1.5f);
    y = y * fmaf(-0.5f * x, y * y, 1.5f);
    return y;
}

// ---------------------------------------------------------------------------
// Projections (SIMT fp32). MODE 0: writes tf32 hi/lo planes of Q/K/V.
// MODE 1: output projection, row-major float out.
// ---------------------------------------------------------------------------
template <int MODE>
__global__ __launch_bounds__(256) void gemm128(
    const float* __restrict__ X0, const float* __restrict__ X1,
    const float* __restrict__ Wt, const float* __restrict__ bias,
    float* __restrict__ Yext, int sel)
{
    __shared__ float As[8][128];
    __shared__ float Bs[8][128];

    const int tid = threadIdx.x;
    const int r0 = blockIdx.y * 128;
    const int c0 = blockIdx.x * 128;

    const float* X;
    int rbase = r0;
    if (MODE == 0) {
        if (r0 >= 4096) { X = X1; rbase = r0 - 4096; }
        else            { X = X0; }
    } else {
        X = sel ? g_Oi : g_Or;
    }

    const int lr = tid >> 1, lc = (tid & 1) << 2;
    const int ty = tid >> 4, tx = tid & 15;

    float acc[8][8];
    #pragma unroll
    for (int i = 0; i < 8; i++)
        #pragma unroll
        for (int j = 0; j < 8; j++) acc[i][j] = 0.f;

    const float* Arow = X  + (size_t)(rbase + lr) * 512 + lc;
    const float* Brow = Wt + (size_t)(c0 + lr) * 512 + lc;

    for (int k0 = 0; k0 < 512; k0 += 8) {
        float4 a = *(const float4*)(Arow + k0);
        float4 b = *(const float4*)(Brow + k0);
        As[lc + 0][lr] = a.x; As[lc + 1][lr] = a.y;
        As[lc + 2][lr] = a.z; As[lc + 3][lr] = a.w;
        Bs[lc + 0][lr] = b.x; Bs[lc + 1][lr] = b.y;
        Bs[lc + 2][lr] = b.z; Bs[lc + 3][lr] = b.w;
        __syncthreads();
        #pragma unroll
        for (int k = 0; k < 8; k++) {
            float av[8], bv[8];
            *(float4*)&av[0] = *(const float4*)&As[k][ty * 8];
            *(float4*)&av[4] = *(const float4*)&As[k][ty * 8 + 4];
            *(float4*)&bv[0] = *(const float4*)&Bs[k][tx * 8];
            *(float4*)&bv[4] = *(const float4*)&Bs[k][tx * 8 + 4];
            #pragma unroll
            for (int i = 0; i < 8; i++)
                #pragma unroll
                for (int j = 0; j < 8; j++)
                    acc[i][j] = fmaf(av[i], bv[j], acc[i][j]);
        }
        __syncthreads();
    }

    #pragma unroll
    for (int i = 0; i < 8; i++) {
        const int r = r0 + ty * 8 + i;
        #pragma unroll
        for (int j = 0; j < 8; j++) {
            const int c = c0 + tx * 8 + j;
            float v = acc[i][j] + bias[c];
            if (MODE == 0) {
                const int ri = r >> 12;
                const int bl = r & 4095;
                const int bb = bl >> 11;
                const int l  = bl & 2047;
                const int h  = c >> 6;
                const int dh = c & 63;
                size_t idx = ((((size_t)ri * QB + bb) * QH + h) * QL + l) * QDh + dh;
                uint32_t* dH = (sel == 0) ? g_Qh : (sel == 1) ? g_Kh : g_Vh;
                uint32_t* dL = (sel == 0) ? g_Ql : (sel == 1) ? g_Kl : g_Vl;
                uint32_t hh, ll; f2tf(v, hh, ll);
                dH[idx] = hh; dL[idx] = ll;
            } else {
                Yext[(size_t)r * 512 + c] = v;
            }
        }
    }
}

// ---------------------------------------------------------------------------
// QK on tensor cores. Block: 128 q x 64 n, 8 warps (warp tile 16x64).
// Sr = QrKr + QiKi ; Si = QrKi + (-Qi)Kr.  Split-tf32, 3 passes/product.
// ---------------------------------------------------------------------------
__global__ __launch_bounds__(256) void qk_mma()
{
    __shared__ uint32_t sB[4][32 * 72];   // KrH,KrL,KiH,KiL  [dh][n] pitch 72

    const int bh = blockIdx.z;
    const int q0 = blockIdx.y * 128;
    const int n0 = blockIdx.x * 64;
    const int tid = threadIdx.x;
    const int warp = tid >> 5, lane = tid & 31;
    const int g = lane >> 2, t = lane & 3;
    const int qw = q0 + warp * 16;

    const size_t hb = (size_t)bh * QL * QDh;
    const uint32_t* QrH = g_Qh + hb;
    const uint32_t* QrL = g_Ql + hb;
    const uint32_t* QiH = g_Qh + RIOFF + hb;
    const uint32_t* QiL = g_Ql + RIOFF + hb;
    const uint32_t* Ks[4] = { g_Kh + hb, g_Kl + hb,
                              g_Kh + RIOFF + hb, g_Kl + RIOFF + hb };

    float Sr[8][4], Si[8][4];
    #pragma unroll
    for (int i = 0; i < 8; i++)
        #pragma unroll
        for (int j = 0; j < 4; j++) { Sr[i][j] = 0.f; Si[i][j] = 0.f; }

    #pragma unroll
    for (int kc = 0; kc < 2; ++kc) {
        __syncthreads();
        #pragma unroll
        for (int it = 0; it < 2; ++it) {
            int s = tid + it * 256;
            int n = s & 63, dg = s >> 6;
            #pragma unroll
            for (int p = 0; p < 4; p++) {
                uint4 v = *(const uint4*)(Ks[p] + (size_t)(n0 + n) * QDh + kc * 32 + dg * 4);
                sB[p][(dg * 4 + 0) * 72 + n] = v.x;
                sB[p][(dg * 4 + 1) * 72 + n] = v.y;
                sB[p][(dg * 4 + 2) * 72 + n] = v.z;
                sB[p][(dg * 4 + 3) * 72 + n] = v.w;
            }
        }
        __syncthreads();

        #pragma unroll
        for (int ks = 0; ks < 4; ++ks) {
            const int kd = kc * 32 + ks * 8 + t;
            const size_t ra = (size_t)(qw + g) * QDh + kd;
            const size_t rb = ra + (size_t)8 * QDh;
            uint32_t qrh[4] = { QrH[ra], QrH[rb], QrH[ra + 4], QrH[rb + 4] };
            uint32_t qrl[4] = { QrL[ra], QrL[rb], QrL[ra + 4], QrL[rb + 4] };
            uint32_t qih[4] = { QiH[ra], QiH[rb], QiH[ra + 4], QiH[rb + 4] };
            uint32_t qil[4] = { QiL[ra], QiL[rb], QiL[ra + 4], QiL[rb + 4] };
            uint32_t nih[4], nil_[4];
            #pragma unroll
            for (int e = 0; e < 4; e++) {
                nih[e]  = qih[e] ^ 0x80000000u;
                nil_[e] = qil[e] ^ 0x80000000u;
            }
            const int rr1 = (ks * 8 + t) * 72, rr2 = (ks * 8 + t + 4) * 72;
            #pragma unroll
            for (int nt = 0; nt < 8; ++nt) {
                const int cb = nt * 8 + g;
                uint32_t krh0 = sB[0][rr1 + cb], krh1 = sB[0][rr2 + cb];
                uint32_t krl0 = sB[1][rr1 + cb], krl1 = sB[1][rr2 + cb];
                uint32_t kih0 = sB[2][rr1 + cb], kih1 = sB[2][rr2 + cb];
                uint32_t kil0 = sB[3][rr1 + cb], kil1 = sB[3][rr2 + cb];
                mma8(Sr[nt], qrh, krh0, krh1);
                mma8(Sr[nt], qrh, krl0, krl1);
                mma8(Sr[nt], qrl, krh0, krh1);
                mma8(Sr[nt], qih, kih0, kih1);
                mma8(Sr[nt], qih, kil0, kil1);
                mma8(Sr[nt], qil, kih0, kih1);
                mma8(Si[nt], qrh, kih0, kih1);
                mma8(Si[nt], qrh, kil0, kil1);
                mma8(Si[nt], qrl, kih0, kih1);
                mma8(Si[nt], nih, krh0, krh1);
                mma8(Si[nt], nih, krl0, krl1);
                mma8(Si[nt], nil_, krh0, krh1);
            }
        }
    }

    const size_t base = (size_t)bh * QL * QL;
    #pragma unroll
    for (int nt = 0; nt < 8; ++nt) {
        const int col = n0 + nt * 8 + 2 * t;
        size_t o0 = base + (size_t)(qw + g) * QL + col;
        size_t o1 = base + (size_t)(qw + g + 8) * QL + col;
        *(float2*)(g_Sr + o0) = make_float2(Sr[nt][0], Sr[nt][1]);
        *(float2*)(g_Si + o0) = make_float2(Si[nt][0], Si[nt][1]);
        *(float2*)(g_Sr + o1) = make_float2(Sr[nt][2], Sr[nt][3]);
        *(float2*)(g_Si + o1) = make_float2(Si[nt][2], Si[nt][3]);
    }
}

// ---------------------------------------------------------------------------
// Fused softmax + phase: per row compute m, sum; write attention A to output,
// and overwrite g_Sr/g_Si in place with Pc = A*cos(phase), Ps = A*sin(phase).
// All exp/rsqrt on the FMA pipe (no MUFU).  One block (256 thr) per row.
// ---------------------------------------------------------------------------
__global__ __launch_bounds__(256) void phase_kernel(float* __restrict__ attn)
{
    const int row = blockIdx.x;
    float* sr = g_Sr + (size_t)row * QL;
    float* si = g_Si + (size_t)row * QL;
    float* at = attn + (size_t)row * QL;
    const int tid = threadIdx.x;

    float a[8], b[8], e[8];
    float mx = -3.4e38f;
    #pragma unroll
    for (int i = 0; i < 8; i++) {
        int k = i * 256 + tid;
        a[i] = sr[k]; b[i] = si[k];
        float s = (a[i] * a[i] + b[i] * b[i]) * 0.125f;
        e[i] = s;
        mx = fmaxf(mx, s);
    }

    __shared__ float red[256];
    red[tid] = mx;
    __syncthreads();
    #pragma unroll
    for (int off = 128; off > 0; off >>= 1) {
        if (tid < off) red[tid] = fmaxf(red[tid], red[tid + off]);
        __syncthreads();
    }
    const float m = red[0];
    __syncthreads();

    float sum = 0.f;
    #pragma unroll
    for (int i = 0; i < 8; i++) {
        e[i] = exp_neg_fast(e[i] - m);
        sum += e[i];
    }
    red[tid] = sum;
    __syncthreads();
    #pragma unroll
    for (int off = 128; off > 0; off >>= 1) {
        if (tid < off) red[tid] += red[tid + off];
        __syncthreads();
    }
    const float il = 1.0f / red[0];

    #pragma unroll
    for (int i = 0; i < 8; i++) {
        int k = i * 256 + tid;
        float A = e[i] * il;
        at[k] = A;
        float r2 = a[i] * a[i] + b[i] * b[i];
        float cr = 1.f, sn = 0.f;
        if (r2 > 0.f) {
            float inv = rsqrt_fast(r2);
            cr = a[i] * inv; sn = b[i] * inv;
        }
        sr[k] = A * cr;
        si[k] = A * sn;
    }
}

// ---------------------------------------------------------------------------
// AV on tensor cores. P = (Pc, Ps) read from g_Sr/g_Si (phase_kernel output).
// Block: 64 q rows x Dh=64; 8 warps = 4 q-warps x 2 n-warps (16q x 32dh).
// Or = Pc*Vr + (-Ps)*Vi ; Oi = Ps*Vr + Pc*Vi.  Split-tf32, 3 passes.
// ---------------------------------------------------------------------------
__global__ __launch_bounds__(256) void av_mma()
{
    __shared__ uint32_t sV[4][32 * 72];   // VrH,VrL,ViH,ViL  [j][dh] pitch 72

    const int bh = blockIdx.y;
    const int q0 = blockIdx.x * 64;
    const int tid = threadIdx.x;
    const int warp = tid >> 5, lane = tid & 31;
    const int wq = warp >> 1, wn = warp & 1;
    const int g = lane >> 2, t = lane & 3;
    const int qw = q0 + wq * 16;
    const int r0 = qw + g, r1 = r0 + 8;

    const size_t hb = (size_t)bh * QL * QDh;
    const uint32_t* Vp[4] = { g_Vh + hb, g_Vl + hb,
                              g_Vh + RIOFF + hb, g_Vl + RIOFF + hb };

    const size_t sbase = (size_t)bh * QL * QL;
    const float* Pc0 = g_Sr + sbase + (size_t)r0 * QL;
    const float* Pc1 = g_Sr + sbase + (size_t)r1 * QL;
    const float* Ps0 = g_Si + sbase + (size_t)r0 * QL;
    const float* Ps1 = g_Si + sbase + (size_t)r1 * QL;

    float Or[4][4], Oi[4][4];
    #pragma unroll
    for (int i = 0; i < 4; i++)
        #pragma unroll
        for (int j = 0; j < 4; j++) { Or[i][j] = 0.f; Oi[i][j] = 0.f; }

    for (int k0 = 0; k0 < QL; k0 += 32) {
        __syncthreads();
        #pragma unroll
        for (int it = 0; it < 2; ++it) {
            int idx = tid + it * 256;
            int jl = idx >> 4, dq = (idx & 15) * 4;
            #pragma unroll
            for (int p = 0; p < 4; p++) {
                uint4 v = *(const uint4*)(Vp[p] + (size_t)(k0 + jl) * QDh + dq);
                sV[p][jl * 72 + dq + 0] = v.x;
                sV[p][jl * 72 + dq + 1] = v.y;
                sV[p][jl * 72 + dq + 2] = v.z;
                sV[p][jl * 72 + dq + 3] = v.w;
            }
        }
        __syncthreads();

        #pragma unroll
        for (int ks = 0; ks < 4; ++ks) {
            uint32_t ach[4], acl[4], ash[4], asl[4], nsh[4], nsl[4];
            #pragma unroll
            for (int e = 0; e < 4; ++e) {
                const int j = k0 + ks * 8 + t + (e >> 1) * 4;
                const bool hi = e & 1;
                float pc = hi ? Pc1[j] : Pc0[j];
                float ps = hi ? Ps1[j] : Ps0[j];
                f2tf(pc, ach[e], acl[e]);
                f2tf(ps, ash[e], asl[e]);
                nsh[e] = ash[e] ^ 0x80000000u;
                nsl[e] = asl[e] ^ 0x80000000u;
            }
            const int rr1 = (ks * 8 + t) * 72, rr2 = (ks * 8 + t + 4) * 72;
            #pragma unroll
            for (int nt = 0; nt < 4; ++nt) {
                const int cb = wn * 32 + nt * 8 + g;
                uint32_t vrh0 = sV[0][rr1 + cb], vrh1 = sV[0][rr2 + cb];
                uint32_t vrl0 = sV[1][rr1 + cb], vrl1 = sV[1][rr2 + cb];
                uint32_t vih0 = sV[2][rr1 + cb], vih1 = sV[2][rr2 + cb];
                uint32_t vil0 = sV[3][rr1 + cb], vil1 = sV[3][rr2 + cb];
                mma8(Or[nt], ach, vrh0, vrh1);
                mma8(Or[nt], ach, vrl0, vrl1);
                mma8(Or[nt], acl, vrh0, vrh1);
                mma8(Or[nt], nsh, vih0, vih1);
                mma8(Or[nt], nsh, vil0, vil1);
                mma8(Or[nt], nsl, vih0, vih1);
                mma8(Oi[nt], ash, vrh0, vrh1);
                mma8(Oi[nt], ash, vrl0, vrl1);
                mma8(Oi[nt], asl, vrh0, vrh1);
                mma8(Oi[nt], ach, vih0, vih1);
                mma8(Oi[nt], ach, vil0, vil1);
                mma8(Oi[nt], acl, vih0, vih1);
            }
        }
    }

    const int b = bh >> 3, h = bh & 7;
    #pragma unroll
    for (int nt = 0; nt < 4; ++nt) {
        const int dh = wn * 32 + nt * 8 + 2 * t;
        size_t o0 = ((size_t)b * QL + r0) * QD + h * QDh + dh;
        size_t o1 = ((size_t)b * QL + r1) * QD + h * QDh + dh;
        *(float2*)(g_Or + o0) = make_float2(Or[nt][0], Or[nt][1]);
        *(float2*)(g_Oi + o0) = make_float2(Oi[nt][0], Oi[nt][1]);
        *(float2*)(g_Or + o1) = make_float2(Or[nt][2], Or[nt][3]);
        *(float2*)(g_Oi + o1) = make_float2(Oi[nt][2], Oi[nt][3]);
    }
}

// ---------------------------------------------------------------------------

extern "C" void kernel_launch(void* const* d_in, const int* in_sizes, int n_in,
                              void* d_out, int out_size)
{
    const float* wr = (const float*)d_in[0];
    const float* wi = (const float*)d_in[1];
    const float* Wq = (const float*)d_in[2];
    const float* bq = (const float*)d_in[3];
    const float* Wk = (const float*)d_in[4];
    const float* bk = (const float*)d_in[5];
    const float* Wv = (const float*)d_in[6];
    const float* bv = (const float*)d_in[7];
    const float* Wo = (const float*)d_in[8];
    const float* bo = (const float*)d_in[9];

    float* out      = (float*)d_out;
    float* out_real = out;
    float* out_imag = out + (size_t)QB * QL * QD;
    float* attn     = out + (size_t)2 * QB * QL * QD;

    dim3 gProj(4, 64);
    dim3 gOut(4, 32);

    gemm128<0><<<gProj, 256>>>(wr, wi, Wq, bq, nullptr, 0);
    gemm128<0><<<gProj, 256>>>(wr, wi, Wk, bk, nullptr, 1);
    gemm128<0><<<gProj, 256>>>(wr, wi, Wv, bv, nullptr, 2);

    qk_mma<<<dim3(32, 16, 16), 256>>>();
    phase_kernel<<<QBH * QL, 256>>>(attn);
    av_mma<<<dim3(32, 16), 256>>>();

    gemm128<1><<<gOut, 256>>>(nullptr, nullptr, Wo, bo, out_real, 0);
    gemm128<1><<<gOut, 256>>>(nullptr, nullptr, Wo, bo, out_imag, 1);
}